// round 3
// baseline (speedup 1.0000x reference)
#include <cuda_runtime.h>
#include <cuda_bf16.h>
#include <cstdint>

// Embedding gather: out[b, t, :] = weight[idxes[b, t], :]
// idxes: [8, 2048] int32  (in_sizes[0] = 16384)
// weight: [50257, 1024] float32
// out:   [8, 2048, 1024] float32
//
// R3: force-batched MLP. R2's compiler collapsed the 8-load batch to save
// registers (regs=32 observed -> MLP ~1-2). Here the 8 row-loads are issued
// via asm volatile LDG.128, which ptxas cannot reorder/interleave with the
// stores, pinning 8 outstanding loads per thread.

#define FEATURES 1024
#define VEC4_PER_ROW (FEATURES / 4)   // 256
#define ROWS_PER_CTA 8

__global__ __launch_bounds__(256) void embedding_gather_forced_mlp_kernel(
    const int* __restrict__ idxes,
    const float4* __restrict__ weight,
    float4* __restrict__ out,
    int n_rows)
{
    const int t = threadIdx.x;                     // 0..255 = column slot
    const int base = blockIdx.x * ROWS_PER_CTA;

    if (base + ROWS_PER_CTA <= n_rows) {
        int idx[ROWS_PER_CTA];
#pragma unroll
        for (int r = 0; r < ROWS_PER_CTA; r++)
            idx[r] = idxes[base + r];              // broadcast loads

        // Front-batch 8 independent LDG.128s. asm volatile pins the issue
        // order: all 8 loads dispatch before any store can retire a value.
        float4 v[ROWS_PER_CTA];
#pragma unroll
        for (int r = 0; r < ROWS_PER_CTA; r++) {
            const float4* p = weight + (size_t)idx[r] * VEC4_PER_ROW + t;
            asm volatile("ld.global.nc.v4.f32 {%0,%1,%2,%3}, [%4];"
                         : "=f"(v[r].x), "=f"(v[r].y), "=f"(v[r].z), "=f"(v[r].w)
                         : "l"(p));
        }

#pragma unroll
        for (int r = 0; r < ROWS_PER_CTA; r++)
            out[(size_t)(base + r) * VEC4_PER_ROW + t] = v[r];
    } else {
        // Tail (unused for 16384 rows, kept for safety).
        for (int r = 0; r < ROWS_PER_CTA; r++) {
            int row = base + r;
            if (row >= n_rows) break;
            int src = idxes[row];
            out[(size_t)row * VEC4_PER_ROW + t] =
                __ldg(weight + (size_t)src * VEC4_PER_ROW + t);
        }
    }
}

extern "C" void kernel_launch(void* const* d_in, const int* in_sizes, int n_in,
                              void* d_out, int out_size)
{
    const int*    idxes  = (const int*)d_in[0];
    const float4* weight = (const float4*)d_in[1];
    float4*       out    = (float4*)d_out;

    int n_rows = in_sizes[0];      // 8 * 2048 = 16384
    int n_ctas = (n_rows + ROWS_PER_CTA - 1) / ROWS_PER_CTA;

    embedding_gather_forced_mlp_kernel<<<n_ctas, 256>>>(idxes, weight, out, n_rows);
}